// round 11
// baseline (speedup 1.0000x reference)
#include <cuda_runtime.h>

// Problem constants (fixed by the reference)
#define NB   4
#define CC   128
#define HH   50
#define WW   50
#define RR   256
#define PHN  7
#define PWN  7
#define HW   (HH*WW)        // 2500
#define SCALE 0.0625f

// fl(1/7) in f32 = 0x3E124925. XLA rewrites x/7 -> x * fl(1/7). Bit-exact match.
#define RECIP7 0x1.24924ap-3f

// NHWC scratch as float4 quads: 4*2500*32 float4 = 5.12 MB, 16B-aligned.
__device__ float4 g_featT4[NB * HW * (CC / 4)];

// ---------------------------------------------------------------------------
// Transpose NCHW -> NHWC. Per image: 128 x 2500 matrix transpose.
// grid: (79, 4, 4)   block: (32, 8)
// ---------------------------------------------------------------------------
__global__ void nchw_to_nhwc(const float* __restrict__ feat) {
    __shared__ float tile[32][33];
    const int n  = blockIdx.z;
    const int c0 = blockIdx.y * 32;
    const int s0 = blockIdx.x * 32;
    const float* src = feat + (size_t)n * CC * HW;
    float*       dst = (float*)g_featT4 + (size_t)n * HW * CC;

    const int tx = threadIdx.x, ty = threadIdx.y;

    #pragma unroll
    for (int i = 0; i < 32; i += 8) {
        int s = s0 + tx;
        if (s < HW) tile[ty + i][tx] = src[(c0 + ty + i) * HW + s];
    }
    __syncthreads();
    #pragma unroll
    for (int i = 0; i < 32; i += 8) {
        int s = s0 + ty + i;
        if (s < HW) dst[s * CC + (c0 + tx)] = tile[tx][ty + i];
    }
}

// ---------------------------------------------------------------------------
// RoI max-pool: ONE BLOCK PER ROI. 7 warps; warp w = bin column pw=w,
// loops ph=0..6. float4 channels (lane = channel quad). Whole 128x7x7 tile
// staged in shared, then written as fully-coalesced float4 stores (the
// per-roi output block is contiguous in gmem).
// ---------------------------------------------------------------------------
__global__ void __launch_bounds__(224)
roipool_kernel(const float* __restrict__ rois, float* __restrict__ out) {
    __shared__ float stage[PHN * PWN][129];   // [k=ph*7+pw][channel], pad 129

    const int r  = blockIdx.x;
    const int pw = threadIdx.x >> 5;     // warp id == pw bin column
    const int l  = threadIdx.x & 31;     // lane = channel quad

    const float* rp = rois + r * 5;
    const int b  = (int)rp[0];
    const int xs = (int)rintf(__fmul_rn(rp[1], SCALE));
    const int ys = (int)rintf(__fmul_rn(rp[2], SCALE));
    const int xe = (int)rintf(__fmul_rn(rp[3], SCALE));
    const int ye = (int)rintf(__fmul_rn(rp[4], SCALE));

    const float roi_w = (float)max(xe - xs + 1, 1);
    const float roi_h = (float)max(ye - ys + 1, 1);
    const float bin_h = __fmul_rn(roi_h, RECIP7);   // == XLA roi_h / 7
    const float bin_w = __fmul_rn(roi_w, RECIP7);

    int wstart = (int)floorf(__fmul_rn((float)pw,       bin_w)) + xs;
    int wend   = (int)ceilf (__fmul_rn((float)(pw + 1), bin_w)) + xs;
    wstart = min(max(wstart, 0), WW);
    wend   = min(max(wend,   0), WW);
    const int  cols = wend - wstart;
    const bool wany = cols > 0;

    const float4* base = g_featT4 + ((size_t)b * HW + wstart) * (CC / 4) + l;
    const float NEG = -3.4e38f;

    #pragma unroll
    for (int ph = 0; ph < PHN; ph++) {
        int hstart = (int)floorf(__fmul_rn((float)ph,       bin_h)) + ys;
        int hend   = (int)ceilf (__fmul_rn((float)(ph + 1), bin_h)) + ys;
        hstart = min(max(hstart, 0), HH);
        hend   = min(max(hend,   0), HH);

        const bool any = wany && (hend > hstart);
        float4 m0 = make_float4(NEG, NEG, NEG, NEG);
        float4 m1 = m0;

        for (int y = hstart; y + 1 < hend; y += 2) {
            const float4* ra = base + (size_t)(y * WW) * (CC / 4);
            const float4* rb = ra + (size_t)WW * (CC / 4);
            #pragma unroll 4
            for (int x = 0; x < cols; x++) {
                float4 va = __ldg(ra); ra += (CC / 4);
                float4 vb = __ldg(rb); rb += (CC / 4);
                m0.x = fmaxf(m0.x, va.x); m0.y = fmaxf(m0.y, va.y);
                m0.z = fmaxf(m0.z, va.z); m0.w = fmaxf(m0.w, va.w);
                m1.x = fmaxf(m1.x, vb.x); m1.y = fmaxf(m1.y, vb.y);
                m1.z = fmaxf(m1.z, vb.z); m1.w = fmaxf(m1.w, vb.w);
            }
        }
        if ((hend - hstart) & 1) {
            const float4* ra = base + (size_t)((hend - 1) * WW) * (CC / 4);
            #pragma unroll 4
            for (int x = 0; x < cols; x++) {
                float4 va = __ldg(ra); ra += (CC / 4);
                m0.x = fmaxf(m0.x, va.x); m0.y = fmaxf(m0.y, va.y);
                m0.z = fmaxf(m0.z, va.z); m0.w = fmaxf(m0.w, va.w);
            }
        }
        m0.x = fmaxf(m0.x, m1.x); m0.y = fmaxf(m0.y, m1.y);
        m0.z = fmaxf(m0.z, m1.z); m0.w = fmaxf(m0.w, m1.w);
        if (!any) m0 = make_float4(0.f, 0.f, 0.f, 0.f);

        float* sk = stage[ph * PWN + pw] + 4 * l;
        sk[0] = m0.x; sk[1] = m0.y; sk[2] = m0.z; sk[3] = m0.w;
    }
    __syncthreads();

    // Coalesced epilogue: per-roi tile out[r*6272 .. +6272) is contiguous.
    // float4 q covers floats e=4q..4q+3; element e maps to stage[e%49][e/49].
    float4* ob4 = (float4*)(out + (size_t)r * (CC * PHN * PWN));
    #pragma unroll
    for (int q = threadIdx.x; q < (CC * PHN * PWN) / 4; q += 224) {
        int e = 4 * q;
        int c0 = e / 49,       k0 = e - 49 * c0;
        int c1 = (e + 1) / 49, k1 = (e + 1) - 49 * c1;
        int c2 = (e + 2) / 49, k2 = (e + 2) - 49 * c2;
        int c3 = (e + 3) / 49, k3 = (e + 3) - 49 * c3;
        float4 v;
        v.x = stage[k0][c0];
        v.y = stage[k1][c1];
        v.z = stage[k2][c2];
        v.w = stage[k3][c3];
        ob4[q] = v;
    }
}

// ---------------------------------------------------------------------------
extern "C" void kernel_launch(void* const* d_in, const int* in_sizes, int n_in,
                              void* d_out, int out_size) {
    const float* feat = (const float*)d_in[0];   // (4,128,50,50)
    const float* rois = (const float*)d_in[1];   // (256,5)
    float* out = (float*)d_out;                  // (256,128,7,7)

    dim3 tb(32, 8);
    dim3 tg((HW + 31) / 32, CC / 32, NB);        // (79, 4, 4)
    nchw_to_nhwc<<<tg, tb>>>(feat);

    roipool_kernel<<<RR, 224>>>(rois, out);
}

// round 12
// speedup vs baseline: 1.6100x; 1.6100x over previous
#include <cuda_runtime.h>

// Problem constants (fixed by the reference)
#define NB   4
#define CC   128
#define HH   50
#define WW   50
#define RR   256
#define PHN  7
#define PWN  7
#define HW   (HH*WW)        // 2500
#define SCALE 0.0625f

// fl(1/7) in f32 = 0x3E124925. XLA rewrites x/7 -> x * fl(1/7). Bit-exact match.
#define RECIP7 0x1.24924ap-3f

// NHWC scratch as float4 quads: 4*2500*32 float4 = 5.12 MB, 16B-aligned.
__device__ float4 g_featT4[NB * HW * (CC / 4)];

// Precomputed per-roi windows (filled by one block of the transpose kernel).
__device__ int2 g_h2[RR * PHN];   // {hstart, hend}
__device__ int2 g_w2[RR * PWN];   // {wstart, wend}
__device__ int  g_b [RR];         // batch index

// ---------------------------------------------------------------------------
// Transpose NCHW -> NHWC; block (0,0,0) additionally decodes all roi windows.
// grid: (79, 4, 4)   block: (32, 8) = 256 threads
// ---------------------------------------------------------------------------
__global__ void nchw_to_nhwc(const float* __restrict__ feat,
                             const float* __restrict__ rois) {
    __shared__ float tile[32][33];
    const int n  = blockIdx.z;
    const int c0 = blockIdx.y * 32;
    const int s0 = blockIdx.x * 32;
    const float* src = feat + (size_t)n * CC * HW;
    float*       dst = (float*)g_featT4 + (size_t)n * HW * CC;

    const int tx = threadIdx.x, ty = threadIdx.y;
    const int tid = ty * 32 + tx;

    // --- roi decode (one designated block; 1 thread = 1 roi) --------------
    if (blockIdx.x == 0 && blockIdx.y == 0 && blockIdx.z == 0) {
        const int r = tid;                      // 256 threads == 256 rois
        const float* rp = rois + r * 5;
        const int b  = (int)rp[0];
        const int xs = (int)rintf(__fmul_rn(rp[1], SCALE));
        const int ys = (int)rintf(__fmul_rn(rp[2], SCALE));
        const int xe = (int)rintf(__fmul_rn(rp[3], SCALE));
        const int ye = (int)rintf(__fmul_rn(rp[4], SCALE));
        const float bin_h = __fmul_rn((float)max(ye - ys + 1, 1), RECIP7);
        const float bin_w = __fmul_rn((float)max(xe - xs + 1, 1), RECIP7);
        g_b[r] = b;
        #pragma unroll
        for (int m = 0; m < PHN; m++) {
            int hs = (int)floorf(__fmul_rn((float)m,       bin_h)) + ys;
            int he = (int)ceilf (__fmul_rn((float)(m + 1), bin_h)) + ys;
            g_h2[r * PHN + m] = make_int2(min(max(hs, 0), HH), min(max(he, 0), HH));
            int ws = (int)floorf(__fmul_rn((float)m,       bin_w)) + xs;
            int we = (int)ceilf (__fmul_rn((float)(m + 1), bin_w)) + xs;
            g_w2[r * PWN + m] = make_int2(min(max(ws, 0), WW), min(max(we, 0), WW));
        }
    }

    // --- transpose --------------------------------------------------------
    #pragma unroll
    for (int i = 0; i < 32; i += 8) {
        int s = s0 + tx;
        if (s < HW) tile[ty + i][tx] = src[(c0 + ty + i) * HW + s];
    }
    __syncthreads();
    #pragma unroll
    for (int i = 0; i < 32; i += 8) {
        int s = s0 + ty + i;
        if (s < HW) dst[s * CC + (c0 + tx)] = tile[tx][ty + i];
    }
}

// ---------------------------------------------------------------------------
// RoI max-pool on NHWC, float4 channels, ONE WARP PER BIN (round-10 shape).
// grid: (7, 256); block: 224 = 7 warps; warp w owns pw=w; lane = channel quad.
// Prologue is now just three table loads; dual y-row max chains for 2x MLP.
// ---------------------------------------------------------------------------
__global__ void __launch_bounds__(224)
roipool_kernel(float* __restrict__ out) {
    __shared__ float4 stage4[PWN][33];   // [pw][lane], padded

    const int r  = blockIdx.y;
    const int ph = blockIdx.x;
    const int pw = threadIdx.x >> 5;
    const int l  = threadIdx.x & 31;

    const int2 hse = g_h2[r * PHN + ph];   // uniform across block
    const int2 wse = g_w2[r * PWN + pw];   // per warp
    const int  b   = g_b[r];

    const int hstart = hse.x, hend = hse.y;
    const int wstart = wse.x, wend = wse.y;
    const int cols = wend - wstart;
    const bool any = (hend > hstart) && (cols > 0);

    const float4* base = g_featT4 + ((size_t)b * HW + wstart) * (CC / 4) + l;
    const float NEG = -3.4e38f;
    float4 m0 = make_float4(NEG, NEG, NEG, NEG);
    float4 m1 = m0;

    for (int y = hstart; y + 1 < hend; y += 2) {
        const float4* ra = base + (size_t)(y * WW) * (CC / 4);
        const float4* rb = ra + (size_t)WW * (CC / 4);
        #pragma unroll 4
        for (int x = 0; x < cols; x++) {
            float4 va = __ldg(ra); ra += (CC / 4);
            float4 vb = __ldg(rb); rb += (CC / 4);
            m0.x = fmaxf(m0.x, va.x); m0.y = fmaxf(m0.y, va.y);
            m0.z = fmaxf(m0.z, va.z); m0.w = fmaxf(m0.w, va.w);
            m1.x = fmaxf(m1.x, vb.x); m1.y = fmaxf(m1.y, vb.y);
            m1.z = fmaxf(m1.z, vb.z); m1.w = fmaxf(m1.w, vb.w);
        }
    }
    if ((hend - hstart) & 1) {
        const float4* ra = base + (size_t)((hend - 1) * WW) * (CC / 4);
        #pragma unroll 4
        for (int x = 0; x < cols; x++) {
            float4 va = __ldg(ra); ra += (CC / 4);
            m0.x = fmaxf(m0.x, va.x); m0.y = fmaxf(m0.y, va.y);
            m0.z = fmaxf(m0.z, va.z); m0.w = fmaxf(m0.w, va.w);
        }
    }
    m0.x = fmaxf(m0.x, m1.x); m0.y = fmaxf(m0.y, m1.y);
    m0.z = fmaxf(m0.z, m1.z); m0.w = fmaxf(m0.w, m1.w);
    if (!any) m0 = make_float4(0.f, 0.f, 0.f, 0.f);
    stage4[pw][l] = m0;
    __syncthreads();

    // Cooperative write of the 128x7 tile: out[(r*128+c)*49 + ph*7 + pw]
    const float* sf = (const float*)stage4;   // channel c of bin pw: pw*132 + c
    float* ob = out + (size_t)r * CC * (PHN * PWN) + ph * PWN;
    #pragma unroll
    for (int e = threadIdx.x; e < CC * PWN; e += 224) {
        int c   = e / PWN;
        int pww = e - c * PWN;
        ob[c * (PHN * PWN) + pww] = sf[pww * 132 + c];
    }
}

// ---------------------------------------------------------------------------
extern "C" void kernel_launch(void* const* d_in, const int* in_sizes, int n_in,
                              void* d_out, int out_size) {
    const float* feat = (const float*)d_in[0];   // (4,128,50,50)
    const float* rois = (const float*)d_in[1];   // (256,5)
    float* out = (float*)d_out;                  // (256,128,7,7)

    dim3 tb(32, 8);
    dim3 tg((HW + 31) / 32, CC / 32, NB);        // (79, 4, 4)
    nchw_to_nhwc<<<tg, tb>>>(feat, rois);

    roipool_kernel<<<dim3(PHN, RR), 224>>>(out);
}

// round 13
// speedup vs baseline: 1.6289x; 1.0117x over previous
#include <cuda_runtime.h>

// Problem constants (fixed by the reference)
#define NB   4
#define CC   128
#define HH   50
#define WW   50
#define RR   256
#define PHN  7
#define PWN  7
#define HW   (HH*WW)        // 2500
#define SCALE 0.0625f
#define CQ   (CC / 4)       // 32 channel quads

// fl(1/7) in f32 = 0x3E124925. XLA rewrites x/7 -> x * fl(1/7). Bit-exact match.
#define RECIP7 0x1.24924ap-3f

// NHWC scratch as float4 quads: 4*2500*32 float4 = 5.12 MB, 16B-aligned.
__device__ float4 g_featT4[NB * HW * CQ];

// ---------------------------------------------------------------------------
// Transpose NCHW -> NHWC. Per image: 128 x 2500 matrix transpose.
// grid: (79, 4, 4)   block: (32, 8)
// ---------------------------------------------------------------------------
__global__ void nchw_to_nhwc(const float* __restrict__ feat) {
    __shared__ float tile[32][33];
    const int n  = blockIdx.z;
    const int c0 = blockIdx.y * 32;
    const int s0 = blockIdx.x * 32;
    const float* src = feat + (size_t)n * CC * HW;
    float*       dst = (float*)g_featT4 + (size_t)n * HW * CC;

    const int tx = threadIdx.x, ty = threadIdx.y;

    #pragma unroll
    for (int i = 0; i < 32; i += 8) {
        int s = s0 + tx;
        if (s < HW) tile[ty + i][tx] = src[(c0 + ty + i) * HW + s];
    }
    __syncthreads();
    #pragma unroll
    for (int i = 0; i < 32; i += 8) {
        int s = s0 + ty + i;
        if (s < HW) dst[s * CC + (c0 + tx)] = tile[tx][ty + i];
    }
}

#define FMAX4(acc, v) \
    acc.x = fmaxf(acc.x, v.x); acc.y = fmaxf(acc.y, v.y); \
    acc.z = fmaxf(acc.z, v.z); acc.w = fmaxf(acc.w, v.w);

// ---------------------------------------------------------------------------
// RoI max-pool on NHWC, float4 channels, one warp per bin (round-10 shape),
// inline roi decode (round-10 style), gather in fixed 2x4 clamped-address
// tiles: 8 independent 16B loads per iteration (duplicates are harmless
// under max), no tail code.
// grid: (7, 256); block: 224 = 7 warps; warp w owns pw=w; lane = channel quad.
// ---------------------------------------------------------------------------
__global__ void __launch_bounds__(224)
roipool_kernel(const float* __restrict__ rois, float* __restrict__ out) {
    __shared__ float4 stage4[PWN][33];   // [pw][lane], padded

    const int r  = blockIdx.y;
    const int ph = blockIdx.x;
    const int pw = threadIdx.x >> 5;
    const int l  = threadIdx.x & 31;

    const float* rp = rois + r * 5;
    const int b  = (int)rp[0];
    const int xs = (int)rintf(__fmul_rn(rp[1], SCALE));
    const int ys = (int)rintf(__fmul_rn(rp[2], SCALE));
    const int xe = (int)rintf(__fmul_rn(rp[3], SCALE));
    const int ye = (int)rintf(__fmul_rn(rp[4], SCALE));

    const float bin_h = __fmul_rn((float)max(ye - ys + 1, 1), RECIP7);
    const float bin_w = __fmul_rn((float)max(xe - xs + 1, 1), RECIP7);

    int hstart = (int)floorf(__fmul_rn((float)ph,       bin_h)) + ys;
    int hend   = (int)ceilf (__fmul_rn((float)(ph + 1), bin_h)) + ys;
    hstart = min(max(hstart, 0), HH);
    hend   = min(max(hend,   0), HH);

    int wstart = (int)floorf(__fmul_rn((float)pw,       bin_w)) + xs;
    int wend   = (int)ceilf (__fmul_rn((float)(pw + 1), bin_w)) + xs;
    wstart = min(max(wstart, 0), WW);
    wend   = min(max(wend,   0), WW);

    const int cols = wend - wstart;
    const bool any = (hend > hstart) && (cols > 0);

    const float4* base = g_featT4 + ((size_t)b * HW + wstart) * CQ + l;
    const float NEG = -3.4e38f;
    float4 m0 = make_float4(NEG, NEG, NEG, NEG);
    float4 m1 = m0;

    if (any) {
        const int xm = cols - 1;
        for (int y = hstart; y < hend; y += 2) {
            const int yb = min(y + 1, hend - 1);       // duplicate row OK (max)
            const float4* ra = base + (size_t)(y  * WW) * CQ;
            const float4* rb = base + (size_t)(yb * WW) * CQ;
            for (int x0 = 0; x0 < cols; x0 += 4) {
                const int x1 = min(x0 + 1, xm);        // duplicate col OK (max)
                const int x2 = min(x0 + 2, xm);
                const int x3 = min(x0 + 3, xm);
                float4 a0 = __ldg(ra + (size_t)x0 * CQ);
                float4 a1 = __ldg(ra + (size_t)x1 * CQ);
                float4 a2 = __ldg(ra + (size_t)x2 * CQ);
                float4 a3 = __ldg(ra + (size_t)x3 * CQ);
                float4 b0 = __ldg(rb + (size_t)x0 * CQ);
                float4 b1 = __ldg(rb + (size_t)x1 * CQ);
                float4 b2 = __ldg(rb + (size_t)x2 * CQ);
                float4 b3 = __ldg(rb + (size_t)x3 * CQ);
                FMAX4(m0, a0); FMAX4(m0, a1); FMAX4(m0, a2); FMAX4(m0, a3);
                FMAX4(m1, b0); FMAX4(m1, b1); FMAX4(m1, b2); FMAX4(m1, b3);
            }
        }
        FMAX4(m0, m1);
    } else {
        m0 = make_float4(0.f, 0.f, 0.f, 0.f);
    }
    stage4[pw][l] = m0;
    __syncthreads();

    // Cooperative write of the 128x7 tile: out[(r*128+c)*49 + ph*7 + pw]
    const float* sf = (const float*)stage4;   // channel c of bin pw: pw*132 + c
    float* ob = out + (size_t)r * CC * (PHN * PWN) + ph * PWN;
    #pragma unroll
    for (int e = threadIdx.x; e < CC * PWN; e += 224) {
        int c   = e / PWN;
        int pww = e - c * PWN;
        ob[c * (PHN * PWN) + pww] = sf[pww * 132 + c];
    }
}

// ---------------------------------------------------------------------------
extern "C" void kernel_launch(void* const* d_in, const int* in_sizes, int n_in,
                              void* d_out, int out_size) {
    const float* feat = (const float*)d_in[0];   // (4,128,50,50)
    const float* rois = (const float*)d_in[1];   // (256,5)
    float* out = (float*)d_out;                  // (256,128,7,7)

    dim3 tb(32, 8);
    dim3 tg((HW + 31) / 32, CC / 32, NB);        // (79, 4, 4)
    nchw_to_nhwc<<<tg, tb>>>(feat);

    roipool_kernel<<<dim3(PHN, RR), 224>>>(rois, out);
}

// round 14
// speedup vs baseline: 1.8170x; 1.1155x over previous
#include <cuda_runtime.h>

// Problem constants (fixed by the reference)
#define NB   4
#define CC   128
#define HH   50
#define WW   50
#define RR   256
#define PHN  7
#define PWN  7
#define HW   (HH*WW)        // 2500
#define SCALE 0.0625f
#define CQ   (CC / 4)       // 32 channel quads

// fl(1/7) in f32 = 0x3E124925. XLA rewrites x/7 -> x * fl(1/7). Bit-exact match.
#define RECIP7 0x1.24924ap-3f

// NHWC scratch as float4 quads: 4*2500*32 float4 = 5.12 MB, 16B-aligned.
__device__ float4 g_featT4[NB * HW * CQ];

// ---------------------------------------------------------------------------
// Transpose NCHW -> NHWC, float4 output stores.
// Each block: 32 spatial positions x all 128 channels.
// grid: (ceil(2500/32)=79, 4)   block: (32, 8) = 256 threads
// Phase 1: coalesced 128B channel-row reads -> shared (4-way STS conflict, cheap).
// Phase 2: conflict-free LDS.128 -> contiguous 512B STG.128 per warp.
// ---------------------------------------------------------------------------
__global__ void __launch_bounds__(256)
nchw_to_nhwc(const float* __restrict__ feat) {
    __shared__ float4 t4[32][33];               // [spatial][quad], padded
    const int n  = blockIdx.y;
    const int s0 = blockIdx.x * 32;
    const float* src = feat + (size_t)n * CC * HW;
    float4* dst4 = g_featT4 + (size_t)n * HW * CQ;

    const int tx = threadIdx.x, ty = threadIdx.y;
    float* tf = (float*)t4;                     // element (s, c) at tf[s*132 + c]

    #pragma unroll
    for (int i = 0; i < 16; i++) {
        int c = ty + 8 * i;                     // warp-uniform channel
        int s = s0 + tx;
        float v = (s < HW) ? src[c * HW + s] : 0.f;
        tf[tx * 132 + c] = v;
    }
    __syncthreads();
    #pragma unroll
    for (int j = 0; j < 4; j++) {
        int sl = ty + 8 * j;
        int s  = s0 + sl;
        if (s < HW) dst4[(size_t)s * CQ + tx] = t4[sl][tx];
    }
}

#define FMAX4(acc, v) \
    acc.x = fmaxf(acc.x, v.x); acc.y = fmaxf(acc.y, v.y); \
    acc.z = fmaxf(acc.z, v.z); acc.w = fmaxf(acc.w, v.w);

// ---------------------------------------------------------------------------
// RoI max-pool on NHWC, float4 channels, one warp per bin (round-10 shape,
// inline decode). Inner gather: 2x2 clamped-address tiles -> 4 independent
// 16B loads in flight; duplicates (odd rows/cols) are harmless under max.
// grid: (7, 256); block: 224 = 7 warps; warp w owns pw=w; lane = channel quad.
// ---------------------------------------------------------------------------
__global__ void __launch_bounds__(224)
roipool_kernel(const float* __restrict__ rois, float* __restrict__ out) {
    __shared__ float4 stage4[PWN][33];   // [pw][lane], padded

    const int r  = blockIdx.y;
    const int ph = blockIdx.x;
    const int pw = threadIdx.x >> 5;
    const int l  = threadIdx.x & 31;

    const float* rp = rois + r * 5;
    const int b  = (int)rp[0];
    const int xs = (int)rintf(__fmul_rn(rp[1], SCALE));
    const int ys = (int)rintf(__fmul_rn(rp[2], SCALE));
    const int xe = (int)rintf(__fmul_rn(rp[3], SCALE));
    const int ye = (int)rintf(__fmul_rn(rp[4], SCALE));

    const float bin_h = __fmul_rn((float)max(ye - ys + 1, 1), RECIP7);
    const float bin_w = __fmul_rn((float)max(xe - xs + 1, 1), RECIP7);

    int hstart = (int)floorf(__fmul_rn((float)ph,       bin_h)) + ys;
    int hend   = (int)ceilf (__fmul_rn((float)(ph + 1), bin_h)) + ys;
    hstart = min(max(hstart, 0), HH);
    hend   = min(max(hend,   0), HH);

    int wstart = (int)floorf(__fmul_rn((float)pw,       bin_w)) + xs;
    int wend   = (int)ceilf (__fmul_rn((float)(pw + 1), bin_w)) + xs;
    wstart = min(max(wstart, 0), WW);
    wend   = min(max(wend,   0), WW);

    const int cols = wend - wstart;
    const bool any = (hend > hstart) && (cols > 0);

    const float4* base = g_featT4 + ((size_t)b * HW + wstart) * CQ + l;
    const float NEG = -3.4e38f;
    float4 m0 = make_float4(NEG, NEG, NEG, NEG);
    float4 m1 = m0;

    if (any) {
        const int xm = cols - 1;
        const int ym = hend - 1;
        for (int y = hstart; y < hend; y += 2) {
            const int yb = min(y + 1, ym);          // duplicate row OK (max)
            const float4* ra = base + (size_t)(y  * WW) * CQ;
            const float4* rb = base + (size_t)(yb * WW) * CQ;
            for (int x0 = 0; x0 < cols; x0 += 2) {
                const int x1 = min(x0 + 1, xm);     // duplicate col OK (max)
                float4 a0 = __ldg(ra + (size_t)x0 * CQ);
                float4 a1 = __ldg(ra + (size_t)x1 * CQ);
                float4 b0 = __ldg(rb + (size_t)x0 * CQ);
                float4 b1 = __ldg(rb + (size_t)x1 * CQ);
                FMAX4(m0, a0); FMAX4(m0, a1);
                FMAX4(m1, b0); FMAX4(m1, b1);
            }
        }
        FMAX4(m0, m1);
    } else {
        m0 = make_float4(0.f, 0.f, 0.f, 0.f);
    }
    stage4[pw][l] = m0;
    __syncthreads();

    // Cooperative write of the 128x7 tile: out[(r*128+c)*49 + ph*7 + pw]
    const float* sf = (const float*)stage4;   // channel c of bin pw: pw*132 + c
    float* ob = out + (size_t)r * CC * (PHN * PWN) + ph * PWN;
    #pragma unroll
    for (int e = threadIdx.x; e < CC * PWN; e += 224) {
        int c   = e / PWN;
        int pww = e - c * PWN;
        ob[c * (PHN * PWN) + pww] = sf[pww * 132 + c];
    }
}

// ---------------------------------------------------------------------------
extern "C" void kernel_launch(void* const* d_in, const int* in_sizes, int n_in,
                              void* d_out, int out_size) {
    const float* feat = (const float*)d_in[0];   // (4,128,50,50)
    const float* rois = (const float*)d_in[1];   // (256,5)
    float* out = (float*)d_out;                  // (256,128,7,7)

    nchw_to_nhwc<<<dim3((HW + 31) / 32, NB), dim3(32, 8)>>>(feat);

    roipool_kernel<<<dim3(PHN, RR), 224>>>(rois, out);
}

// round 15
// speedup vs baseline: 1.8330x; 1.0088x over previous
#include <cuda_runtime.h>

// Problem constants (fixed by the reference)
#define NB   4
#define CC   128
#define HH   50
#define WW   50
#define RR   256
#define PHN  7
#define PWN  7
#define HW   (HH*WW)        // 2500
#define SCALE 0.0625f
#define CQ   (CC / 4)       // 32 channel quads

// fl(1/7) in f32 = 0x3E124925. XLA rewrites x/7 -> x * fl(1/7). Bit-exact match.
#define RECIP7 0x1.24924ap-3f

// NHWC scratch as float4 quads: 4*2500*32 float4 = 5.12 MB, 16B-aligned.
__device__ float4 g_featT4[NB * HW * CQ];

// ---------------------------------------------------------------------------
// Transpose NCHW -> NHWC, float4 output stores (round-14 winner, 2.25us).
// Each block: 32 spatial positions x all 128 channels.
// grid: (79, 4)   block: (32, 8) = 256 threads
// ---------------------------------------------------------------------------
__global__ void __launch_bounds__(256)
nchw_to_nhwc(const float* __restrict__ feat) {
    __shared__ float4 t4[32][33];               // [spatial][quad], padded
    const int n  = blockIdx.y;
    const int s0 = blockIdx.x * 32;
    const float* src = feat + (size_t)n * CC * HW;
    float4* dst4 = g_featT4 + (size_t)n * HW * CQ;

    const int tx = threadIdx.x, ty = threadIdx.y;
    float* tf = (float*)t4;                     // element (s, c) at tf[s*132 + c]

    #pragma unroll
    for (int i = 0; i < 16; i++) {
        int c = ty + 8 * i;                     // warp-uniform channel
        int s = s0 + tx;
        float v = (s < HW) ? src[c * HW + s] : 0.f;
        tf[tx * 132 + c] = v;
    }
    __syncthreads();
    #pragma unroll
    for (int j = 0; j < 4; j++) {
        int sl = ty + 8 * j;
        int s  = s0 + sl;
        if (s < HW) dst4[(size_t)s * CQ + tx] = t4[sl][tx];
    }
}

// ---------------------------------------------------------------------------
// RoI max-pool on NHWC, float4 channels, ONE WARP PER BIN — exact round-10
// configuration (measured 10.8us, 40 regs, occ 53%).
// grid: (7, 256); block: 224 = 7 warps; warp w owns pw=w; lane = channel quad.
// ---------------------------------------------------------------------------
__global__ void __launch_bounds__(224)
roipool_kernel(const float* __restrict__ rois, float* __restrict__ out) {
    __shared__ float4 stage4[PWN][33];   // [pw][lane], padded

    const int r  = blockIdx.y;
    const int ph = blockIdx.x;
    const int pw = threadIdx.x >> 5;     // warp id == pw bin
    const int l  = threadIdx.x & 31;     // lane = channel quad

    const float* rp = rois + r * 5;
    const int b  = (int)rp[0];
    const int xs = (int)rintf(__fmul_rn(rp[1], SCALE));
    const int ys = (int)rintf(__fmul_rn(rp[2], SCALE));
    const int xe = (int)rintf(__fmul_rn(rp[3], SCALE));
    const int ye = (int)rintf(__fmul_rn(rp[4], SCALE));

    const float roi_w = (float)max(xe - xs + 1, 1);
    const float roi_h = (float)max(ye - ys + 1, 1);
    const float bin_h = __fmul_rn(roi_h, RECIP7);   // == XLA roi_h / 7
    const float bin_w = __fmul_rn(roi_w, RECIP7);

    int hstart = (int)floorf(__fmul_rn((float)ph,       bin_h)) + ys;
    int hend   = (int)ceilf (__fmul_rn((float)(ph + 1), bin_h)) + ys;
    hstart = min(max(hstart, 0), HH);
    hend   = min(max(hend,   0), HH);

    int wstart = (int)floorf(__fmul_rn((float)pw,       bin_w)) + xs;
    int wend   = (int)ceilf (__fmul_rn((float)(pw + 1), bin_w)) + xs;
    wstart = min(max(wstart, 0), WW);
    wend   = min(max(wend,   0), WW);

    const bool any = (hend > hstart) && (wend > wstart);
    const int cols = wend - wstart;
    const float4* base = g_featT4 + ((size_t)b * HW + wstart) * CQ + l;

    const float NEG = -3.4e38f;
    float4 m0 = make_float4(NEG, NEG, NEG, NEG);
    float4 m1 = m0;

    // Two independent accumulator chains over alternating rows (2x MLP).
    for (int y = hstart; y + 1 < hend; y += 2) {
        const float4* ra = base + (size_t)(y * WW) * CQ;
        const float4* rb = ra + (size_t)WW * CQ;
        #pragma unroll 4
        for (int x = 0; x < cols; x++) {
            float4 va = __ldg(ra); ra += CQ;
            float4 vb = __ldg(rb); rb += CQ;
            m0.x = fmaxf(m0.x, va.x); m0.y = fmaxf(m0.y, va.y);
            m0.z = fmaxf(m0.z, va.z); m0.w = fmaxf(m0.w, va.w);
            m1.x = fmaxf(m1.x, vb.x); m1.y = fmaxf(m1.y, vb.y);
            m1.z = fmaxf(m1.z, vb.z); m1.w = fmaxf(m1.w, vb.w);
        }
    }
    if ((hend - hstart) & 1) {           // tail row
        const float4* ra = base + (size_t)((hend - 1) * WW) * CQ;
        #pragma unroll 4
        for (int x = 0; x < cols; x++) {
            float4 va = __ldg(ra); ra += CQ;
            m0.x = fmaxf(m0.x, va.x); m0.y = fmaxf(m0.y, va.y);
            m0.z = fmaxf(m0.z, va.z); m0.w = fmaxf(m0.w, va.w);
        }
    }
    m0.x = fmaxf(m0.x, m1.x); m0.y = fmaxf(m0.y, m1.y);
    m0.z = fmaxf(m0.z, m1.z); m0.w = fmaxf(m0.w, m1.w);
    if (!any) m0 = make_float4(0.f, 0.f, 0.f, 0.f);
    stage4[pw][l] = m0;
    __syncthreads();

    // Cooperative write of the 128x7 tile: out[(r*128+c)*49 + ph*7 + pw]
    const float* sf = (const float*)stage4;   // channel c of bin pw: pw*132 + c
    float* ob = out + (size_t)r * CC * (PHN * PWN) + ph * PWN;
    #pragma unroll
    for (int e = threadIdx.x; e < CC * PWN; e += 224) {
        int c   = e / PWN;
        int pww = e - c * PWN;
        ob[c * (PHN * PWN) + pww] = sf[pww * 132 + c];
    }
}

// ---------------------------------------------------------------------------
extern "C" void kernel_launch(void* const* d_in, const int* in_sizes, int n_in,
                              void* d_out, int out_size) {
    const float* feat = (const float*)d_in[0];   // (4,128,50,50)
    const float* rois = (const float*)d_in[1];   // (256,5)
    float* out = (float*)d_out;                  // (256,128,7,7)

    nchw_to_nhwc<<<dim3((HW + 31) / 32, NB), dim3(32, 8)>>>(feat);

    roipool_kernel<<<dim3(PHN, RR), 224>>>(rois, out);
}